// round 10
// baseline (speedup 1.0000x reference)
#include <cuda_runtime.h>
#include <cuda_fp16.h>
#include <cstdint>

#define UPITCH 72            // words per (pix,q) row
#define U_LO   4608
#define W_OFF  9216
#define BUFW   13824         // words per double-buffer slot (3 planes)
#define KOFF_W 27648         // koff table (reused by epilogue staging)
#define SEPP   520
#define SMEM_BYTES ((64 * SEPP + 576) * 4)   // epilogue is the max user

__device__ float g_xTp[64 * 34 * 34 * 64];   // [c][hp][wp][b], raw f32

__device__ __forceinline__ uint32_t pkh2(float x, float y) {
    __half2 h = __halves2half2(__float2half_rn(x), __float2half_rn(y));
    return *(uint32_t*)&h;
}
#define MMAF16(d, a, b) asm volatile( \
    "mma.sync.aligned.m16n8k16.row.col.f32.f16.f16.f32 " \
    "{%0,%1,%2,%3},{%4,%5,%6,%7},{%8,%9},{%0,%1,%2,%3};" \
    : "+f"((d)[0]), "+f"((d)[1]), "+f"((d)[2]), "+f"((d)[3]) \
    : "r"((a)[0]), "r"((a)[1]), "r"((a)[2]), "r"((a)[3]), "r"((b)[0]), "r"((b)[1]))

// ---------------------------------------------------------------------------
__global__ void border_kernel() {
    int idx = blockIdx.x * 256 + threadIdx.x;      // 64c * 132 cells * 16 (b/4)
    if (idx >= 64 * 132 * 16) return;
    int b4 = idx & 15, r = idx >> 4;
    int c = r / 132, cell = r % 132;
    int hp, wp;
    if (cell < 34)       { hp = 0;  wp = cell; }
    else if (cell < 68)  { hp = 33; wp = cell - 34; }
    else if (cell < 100) { hp = cell - 68 + 1;  wp = 0; }
    else                 { hp = cell - 100 + 1; wp = 33; }
    *(float4*)&g_xTp[((c * 34 + hp) * 34 + wp) * 64 + b4 * 4] = make_float4(0.f, 0.f, 0.f, 0.f);
}

__global__ void transpose_kernel(const float* __restrict__ x) {
    __shared__ float t[32][65];
    int c = blockIdx.x & 63, h = blockIdx.x >> 6, tid = threadIdx.x;
    int w = tid & 31, b0 = tid >> 5;
#pragma unroll
    for (int p = 0; p < 8; p++)
        t[w][b0 * 8 + p] = x[(((b0 * 8 + p) * 64 + c) * 32 + h) * 32 + w];
    __syncthreads();
    int b = tid & 63, wq = tid >> 6;
#pragma unroll
    for (int p = 0; p < 8; p++) {
        int ww = wq * 8 + p;
        g_xTp[((c * 34 + h + 1) * 34 + ww + 1) * 64 + b] = t[ww][b];
    }
}

// ---------------------------------------------------------------------------
__global__ __launch_bounds__(512, 1)
void lc_kernel(const float* __restrict__ weight, const float* __restrict__ bias,
               float* __restrict__ out) {
    extern __shared__ float sm[];
    uint32_t* usm = (uint32_t*)sm;
    int* koff = (int*)(sm + KOFF_W);

    const int tid = threadIdx.x, lane = tid & 31, wrp = tid >> 5;
    const int pix = wrp >> 1, nh = wrp & 1;
    const int l0 = blockIdx.x << 3, h = l0 >> 5, w0 = l0 & 31;
    const int cq = lane & 3, rr = lane >> 2;

    for (int k = tid; k < 576; k += 512) {
        int c = k / 9, r = k - 9 * c, i = r / 3, j = r - 3 * i;
        koff[k] = (c * 1156 + i * 34 + j) * 64;
    }
    __syncthreads();

    // ---- u fill mapping: unit s in {0,1}: (pix_u, q, b4) ----
    const int ub4 = tid & 15, uq = (tid >> 4) & 7, up = tid >> 7;  // up 0..3
    const int upix0 = up, upix1 = up + 4;
    const int ubase0 = (h * 34 + w0 + upix0) * 64 + ub4 * 4;
    const int ubase1 = (h * 34 + w0 + upix1) * 64 + ub4 * 4;

    // ---- w fill mapping: (o, q) ----
    const int wo = tid & 63, wq = tid >> 6;                        // wq 0..7
    const float* wsrc0 = weight + ((size_t)wo * 576 + 2 * wq) * 1024 + l0;

    uint32_t uh[2][4], ul[2][4], wst[8];

    auto ldg_u = [&](int ch) {
#pragma unroll
        for (int s = 0; s < 2; s++) {
            int k0 = ch * 16 + 2 * uq;
            int base = s ? ubase1 : ubase0;
            float4 v0 = *(const float4*)(g_xTp + koff[k0] + base);
            float4 v1 = *(const float4*)(g_xTp + koff[k0 + 1] + base);
            float a[4] = { v0.x, v0.y, v0.z, v0.w };
            float b[4] = { v1.x, v1.y, v1.z, v1.w };
#pragma unroll
            for (int e = 0; e < 4; e++) {
                __half h0 = __float2half_rn(a[e]);
                __half h1 = __float2half_rn(b[e]);
                __half g0 = __float2half_rn(a[e] - __half2float(h0));
                __half g1 = __float2half_rn(b[e] - __half2float(h1));
                __half2 hh = __halves2half2(h0, h1), gg = __halves2half2(g0, g1);
                uh[s][e] = *(uint32_t*)&hh;
                ul[s][e] = *(uint32_t*)&gg;
            }
        }
    };
    auto ldg_w = [&](int ch) {
        const float* s0 = wsrc0 + (size_t)ch * 16 * 1024;
        const float* s1 = s0 + 1024;
        float4 a0 = *(const float4*)s0, a1 = *(const float4*)(s0 + 4);
        float4 b0 = *(const float4*)s1, b1 = *(const float4*)(s1 + 4);
        float pa[8] = { a0.x, a0.y, a0.z, a0.w, a1.x, a1.y, a1.z, a1.w };
        float pb[8] = { b0.x, b0.y, b0.z, b0.w, b1.x, b1.y, b1.z, b1.w };
#pragma unroll
        for (int e = 0; e < 8; e++) wst[e] = pkh2(pa[e], pb[e]);
    };
    auto sts_all = [&](int buf) {
        // u: 2 x (STS.128 hi + STS.128 lo)
#pragma unroll
        for (int s = 0; s < 2; s++) {
            int pixu = s ? upix1 : upix0;
            uint32_t* d = usm + buf * BUFW + (pixu * 8 + uq) * UPITCH + ub4 * 4;
            *(uint4*)d           = make_uint4(uh[s][0], uh[s][1], uh[s][2], uh[s][3]);
            *(uint4*)(d + U_LO)  = make_uint4(ul[s][0], ul[s][1], ul[s][2], ul[s][3]);
        }
        // w: 8 x STS.32, lanes o-consecutive -> conflict-free
        uint32_t* dw = usm + buf * BUFW + W_OFF + wq * UPITCH + wo;
#pragma unroll
        for (int e = 0; e < 8; e++) dw[e * (8 * UPITCH)] = wst[e];
    };

    float acc[16][4];
#pragma unroll
    for (int i = 0; i < 16; i++)
#pragma unroll
        for (int j = 0; j < 4; j++) acc[i][j] = 0.f;

    ldg_u(0); ldg_w(0);

    for (int ch = 0; ch < 36; ch++) {
        const int buf = ch & 1;
        sts_all(buf);
        __syncthreads();
        if (ch < 35) { ldg_u(ch + 1); ldg_w(ch + 1); }

        const uint32_t* AH = usm + buf * BUFW + pix * 576 + cq * UPITCH + rr;
        const uint32_t* BB = usm + buf * BUFW + W_OFF + pix * 576 + cq * UPITCH + nh * 32 + rr;
        uint32_t bfr[4][2];
#pragma unroll
        for (int nt = 0; nt < 4; nt++) {
            bfr[nt][0] = BB[nt * 8];
            bfr[nt][1] = BB[4 * UPITCH + nt * 8];
        }
#pragma unroll
        for (int mt = 0; mt < 4; mt++) {
            uint32_t ah[4], al[4];
            ah[0] = AH[mt * 16];               ah[1] = AH[mt * 16 + 8];
            ah[2] = AH[4 * UPITCH + mt * 16];  ah[3] = AH[4 * UPITCH + mt * 16 + 8];
            al[0] = AH[U_LO + mt * 16];              al[1] = AH[U_LO + mt * 16 + 8];
            al[2] = AH[U_LO + 4 * UPITCH + mt * 16]; al[3] = AH[U_LO + 4 * UPITCH + mt * 16 + 8];
#pragma unroll
            for (int nt = 0; nt < 4; nt++) {
                MMAF16(acc[mt * 4 + nt], ah, bfr[nt]);
                MMAF16(acc[mt * 4 + nt], al, bfr[nt]);
            }
        }
        // single sync per chunk: buf is safe to rewrite two iterations later
    }
    __syncthreads();   // protect smem before epilogue staging overwrites it

    // ---- epilogue: stage D to smem, then coalesced 32B output lines ----
    float* sep = sm;   // [b][o*8 + pix], pitch SEPP per b
#pragma unroll
    for (int mt = 0; mt < 4; mt++)
#pragma unroll
        for (int nt = 0; nt < 4; nt++) {
            const float* d = acc[mt * 4 + nt];
            int b_ = mt * 16 + rr;
            int o_ = nh * 32 + nt * 8 + cq * 2;
            sep[b_ * SEPP + o_ * 8 + pix]             = d[0];
            sep[b_ * SEPP + (o_ + 1) * 8 + pix]       = d[1];
            sep[(b_ + 8) * SEPP + o_ * 8 + pix]       = d[2];
            sep[(b_ + 8) * SEPP + (o_ + 1) * 8 + pix] = d[3];
        }
    __syncthreads();
#pragma unroll
    for (int it = 0; it < 8; it++) {
        int unit = tid + (it << 9);
        int o = unit & 63, b = unit >> 6;
        const float* sp = sep + b * SEPP + o * 8;
        float4 v0 = *(const float4*)sp;
        float4 v1 = *(const float4*)(sp + 4);
        float4 g0 = *(const float4*)(bias + o * 1024 + l0);
        float4 g1 = *(const float4*)(bias + o * 1024 + l0 + 4);
        float* dp = out + ((size_t)(b * 64 + o)) * 1024 + l0;
        *(float4*)dp       = make_float4(v0.x + g0.x, v0.y + g0.y, v0.z + g0.z, v0.w + g0.w);
        *(float4*)(dp + 4) = make_float4(v1.x + g1.x, v1.y + g1.y, v1.z + g1.z, v1.w + g1.w);
    }
}

// ---------------------------------------------------------------------------
extern "C" void kernel_launch(void* const* d_in, const int* in_sizes, int n_in,
                              void* d_out, int out_size) {
    const float* x      = (const float*)d_in[0];
    const float* weight = (const float*)d_in[1];
    const float* bias   = (const float*)d_in[2];
    float* out = (float*)d_out;

    cudaFuncSetAttribute(lc_kernel, cudaFuncAttributeMaxDynamicSharedMemorySize, SMEM_BYTES);

    border_kernel<<<(64 * 132 * 16 + 255) / 256, 256>>>();
    transpose_kernel<<<64 * 32, 256>>>(x);
    lc_kernel<<<128, 512, SMEM_BYTES>>>(weight, bias, out);
}

// round 11
// speedup vs baseline: 1.0867x; 1.0867x over previous
#include <cuda_runtime.h>
#include <cuda_fp16.h>
#include <cstdint>

#define UPITCH 72            // words per (pix,q) row
#define W_OFF  4608          // w plane offset (u plane: 8*8*72 = 4608 words)
#define BUFW   9216          // words per double-buffer slot (2 planes)
#define KOFF_W 18432         // koff table
#define SEPP   520
#define SMEM_BYTES ((64 * SEPP + 576) * 4)   // epilogue is the max user

__device__ float g_xTp[64 * 34 * 34 * 64];   // [c][hp][wp][b], raw f32

__device__ __forceinline__ uint32_t pkh2(float x, float y) {
    __half2 h = __halves2half2(__float2half_rn(x), __float2half_rn(y));
    return *(uint32_t*)&h;
}
#define MMAF16(d, a, b) asm volatile( \
    "mma.sync.aligned.m16n8k16.row.col.f32.f16.f16.f32 " \
    "{%0,%1,%2,%3},{%4,%5,%6,%7},{%8,%9},{%0,%1,%2,%3};" \
    : "+f"((d)[0]), "+f"((d)[1]), "+f"((d)[2]), "+f"((d)[3]) \
    : "r"((a)[0]), "r"((a)[1]), "r"((a)[2]), "r"((a)[3]), "r"((b)[0]), "r"((b)[1]))

// ---------------------------------------------------------------------------
__global__ void border_kernel() {
    int idx = blockIdx.x * 256 + threadIdx.x;      // 64c * 132 cells * 16 (b/4)
    if (idx >= 64 * 132 * 16) return;
    int b4 = idx & 15, r = idx >> 4;
    int c = r / 132, cell = r % 132;
    int hp, wp;
    if (cell < 34)       { hp = 0;  wp = cell; }
    else if (cell < 68)  { hp = 33; wp = cell - 34; }
    else if (cell < 100) { hp = cell - 68 + 1;  wp = 0; }
    else                 { hp = cell - 100 + 1; wp = 33; }
    *(float4*)&g_xTp[((c * 34 + hp) * 34 + wp) * 64 + b4 * 4] = make_float4(0.f, 0.f, 0.f, 0.f);
}

__global__ void transpose_kernel(const float* __restrict__ x) {
    __shared__ float t[32][65];
    int c = blockIdx.x & 63, h = blockIdx.x >> 6, tid = threadIdx.x;
    int w = tid & 31, b0 = tid >> 5;
#pragma unroll
    for (int p = 0; p < 8; p++)
        t[w][b0 * 8 + p] = x[(((b0 * 8 + p) * 64 + c) * 32 + h) * 32 + w];
    __syncthreads();
    int b = tid & 63, wq = tid >> 6;
#pragma unroll
    for (int p = 0; p < 8; p++) {
        int ww = wq * 8 + p;
        g_xTp[((c * 34 + h + 1) * 34 + ww + 1) * 64 + b] = t[ww][b];
    }
}

// ---------------------------------------------------------------------------
__global__ __launch_bounds__(512, 1)
void lc_kernel(const float* __restrict__ weight, const float* __restrict__ bias,
               float* __restrict__ out) {
    extern __shared__ float sm[];
    uint32_t* usm = (uint32_t*)sm;
    int* koff = (int*)(sm + KOFF_W);

    const int tid = threadIdx.x, lane = tid & 31, wrp = tid >> 5;
    const int pix = wrp >> 1, nh = wrp & 1;
    const int l0 = blockIdx.x << 3, h = l0 >> 5, w0 = l0 & 31;
    const int cq = lane & 3, rr = lane >> 2;

    for (int k = tid; k < 576; k += 512) {
        int c = k / 9, r = k - 9 * c, i = r / 3, j = r - 3 * i;
        koff[k] = (c * 1156 + i * 34 + j) * 64;
    }
    __syncthreads();

    // ---- u fill mapping: unit s in {0,1}: (pix_u, q, b4) ----
    const int ub4 = tid & 15, uq = (tid >> 4) & 7, up = tid >> 7;  // up 0..3
    const int upix0 = up, upix1 = up + 4;
    const int ubase0 = (h * 34 + w0 + upix0) * 64 + ub4 * 4;
    const int ubase1 = (h * 34 + w0 + upix1) * 64 + ub4 * 4;

    // ---- w fill mapping: (o, q) ----
    const int wo = tid & 63, wq = tid >> 6;                        // wq 0..7
    const float* wsrc0 = weight + ((size_t)wo * 576 + 2 * wq) * 1024 + l0;

    uint32_t uh[2][4], wst[8];

    auto ldg_u = [&](int ch) {
#pragma unroll
        for (int s = 0; s < 2; s++) {
            int k0 = ch * 16 + 2 * uq;
            int base = s ? ubase1 : ubase0;
            float4 v0 = *(const float4*)(g_xTp + koff[k0] + base);
            float4 v1 = *(const float4*)(g_xTp + koff[k0 + 1] + base);
            float a[4] = { v0.x, v0.y, v0.z, v0.w };
            float b[4] = { v1.x, v1.y, v1.z, v1.w };
#pragma unroll
            for (int e = 0; e < 4; e++)
                uh[s][e] = pkh2(a[e], b[e]);
        }
    };
    auto ldg_w = [&](int ch) {
        const float* s0 = wsrc0 + (size_t)ch * 16 * 1024;
        const float* s1 = s0 + 1024;
        float4 a0 = *(const float4*)s0, a1 = *(const float4*)(s0 + 4);
        float4 b0 = *(const float4*)s1, b1 = *(const float4*)(s1 + 4);
        float pa[8] = { a0.x, a0.y, a0.z, a0.w, a1.x, a1.y, a1.z, a1.w };
        float pb[8] = { b0.x, b0.y, b0.z, b0.w, b1.x, b1.y, b1.z, b1.w };
#pragma unroll
        for (int e = 0; e < 8; e++) wst[e] = pkh2(pa[e], pb[e]);
    };
    auto sts_all = [&](int buf) {
        // u: 2 x STS.128
#pragma unroll
        for (int s = 0; s < 2; s++) {
            int pixu = s ? upix1 : upix0;
            uint32_t* d = usm + buf * BUFW + (pixu * 8 + uq) * UPITCH + ub4 * 4;
            *(uint4*)d = make_uint4(uh[s][0], uh[s][1], uh[s][2], uh[s][3]);
        }
        // w: 8 x STS.32, lanes o-consecutive -> conflict-free
        uint32_t* dw = usm + buf * BUFW + W_OFF + wq * UPITCH + wo;
#pragma unroll
        for (int e = 0; e < 8; e++) dw[e * (8 * UPITCH)] = wst[e];
    };

    float acc[16][4];
#pragma unroll
    for (int i = 0; i < 16; i++)
#pragma unroll
        for (int j = 0; j < 4; j++) acc[i][j] = 0.f;

    ldg_u(0); ldg_w(0);

    for (int ch = 0; ch < 36; ch++) {
        const int buf = ch & 1;
        sts_all(buf);
        __syncthreads();
        if (ch < 35) { ldg_u(ch + 1); ldg_w(ch + 1); }

        const uint32_t* AH = usm + buf * BUFW + pix * 576 + cq * UPITCH + rr;
        const uint32_t* BB = usm + buf * BUFW + W_OFF + pix * 576 + cq * UPITCH + nh * 32 + rr;
        uint32_t bfr[4][2];
#pragma unroll
        for (int nt = 0; nt < 4; nt++) {
            bfr[nt][0] = BB[nt * 8];
            bfr[nt][1] = BB[4 * UPITCH + nt * 8];
        }
#pragma unroll
        for (int mt = 0; mt < 4; mt++) {
            uint32_t ah[4];
            ah[0] = AH[mt * 16];               ah[1] = AH[mt * 16 + 8];
            ah[2] = AH[4 * UPITCH + mt * 16];  ah[3] = AH[4 * UPITCH + mt * 16 + 8];
#pragma unroll
            for (int nt = 0; nt < 4; nt++)
                MMAF16(acc[mt * 4 + nt], ah, bfr[nt]);
        }
        // single sync per chunk: buf is safe to rewrite two iterations later
    }
    __syncthreads();   // protect smem before epilogue staging overwrites it

    // ---- epilogue: stage D to smem, then coalesced 32B output lines ----
    float* sep = sm;   // [b][o*8 + pix], pitch SEPP per b
#pragma unroll
    for (int mt = 0; mt < 4; mt++)
#pragma unroll
        for (int nt = 0; nt < 4; nt++) {
            const float* d = acc[mt * 4 + nt];
            int b_ = mt * 16 + rr;
            int o_ = nh * 32 + nt * 8 + cq * 2;
            sep[b_ * SEPP + o_ * 8 + pix]             = d[0];
            sep[b_ * SEPP + (o_ + 1) * 8 + pix]       = d[1];
            sep[(b_ + 8) * SEPP + o_ * 8 + pix]       = d[2];
            sep[(b_ + 8) * SEPP + (o_ + 1) * 8 + pix] = d[3];
        }
    __syncthreads();
#pragma unroll
    for (int it = 0; it < 8; it++) {
        int unit = tid + (it << 9);
        int o = unit & 63, b = unit >> 6;
        const float* sp = sep + b * SEPP + o * 8;
        float4 v0 = *(const float4*)sp;
        float4 v1 = *(const float4*)(sp + 4);
        float4 g0 = *(const float4*)(bias + o * 1024 + l0);
        float4 g1 = *(const float4*)(bias + o * 1024 + l0 + 4);
        float* dp = out + ((size_t)(b * 64 + o)) * 1024 + l0;
        *(float4*)dp       = make_float4(v0.x + g0.x, v0.y + g0.y, v0.z + g0.z, v0.w + g0.w);
        *(float4*)(dp + 4) = make_float4(v1.x + g1.x, v1.y + g1.y, v1.z + g1.z, v1.w + g1.w);
    }
}

// ---------------------------------------------------------------------------
extern "C" void kernel_launch(void* const* d_in, const int* in_sizes, int n_in,
                              void* d_out, int out_size) {
    const float* x      = (const float*)d_in[0];
    const float* weight = (const float*)d_in[1];
    const float* bias   = (const float*)d_in[2];
    float* out = (float*)d_out;

    cudaFuncSetAttribute(lc_kernel, cudaFuncAttributeMaxDynamicSharedMemorySize, SMEM_BYTES);

    border_kernel<<<(64 * 132 * 16 + 255) / 256, 256>>>();
    transpose_kernel<<<64 * 32, 256>>>(x);
    lc_kernel<<<128, 512, SMEM_BYTES>>>(weight, bias, out);
}

// round 12
// speedup vs baseline: 1.7454x; 1.6062x over previous
#include <cuda_runtime.h>
#include <cuda_fp16.h>
#include <cstdint>

#define UQ 72               // u q-stride (words)
#define UL 576              // u l-stride (8*72)
#define UBUFW 9216          // 16 l * 576
#define WQS 552             // w q-stride (16*34 + 8)
#define WLS 34              // w l-stride (32 o + 2 pad)
#define WBUFW 4416          // 8 * 552
#define SLOTW 13632         // UBUFW + WBUFW
#define KOFF_W 27264        // after 2 slots
#define SEP_BS 34
#define SEP_PS 2176         // 64 * 34
#define SMEM_BYTES (34816 * 4)

__device__ __align__(256) __half g_xh[64 * 34 * 34 * 64];  // [c][hp][wp][b] fp16

__device__ __forceinline__ uint32_t prmt(uint32_t a, uint32_t b, uint32_t s) {
    uint32_t d; asm("prmt.b32 %0,%1,%2,%3;" : "=r"(d) : "r"(a), "r"(b), "r"(s)); return d;
}
__device__ __forceinline__ uint32_t f16x2(float hi, float lo) {
    uint32_t d; asm("cvt.rn.f16x2.f32 %0,%1,%2;" : "=r"(d) : "f"(hi), "f"(lo)); return d;
}
#define MMAF16(d, a, b) asm volatile( \
    "mma.sync.aligned.m16n8k16.row.col.f32.f16.f16.f32 " \
    "{%0,%1,%2,%3},{%4,%5,%6,%7},{%8,%9},{%0,%1,%2,%3};" \
    : "+f"((d)[0]), "+f"((d)[1]), "+f"((d)[2]), "+f"((d)[3]) \
    : "r"((a)[0]), "r"((a)[1]), "r"((a)[2]), "r"((a)[3]), "r"((b)[0]), "r"((b)[1]))

// ---------------------------------------------------------------------------
__global__ void border_kernel() {
    int idx = blockIdx.x * 256 + threadIdx.x;      // 64c * 132 cells * 8 (b/8)
    if (idx >= 64 * 132 * 8) return;
    int g8 = idx & 7, r = idx >> 3;
    int c = r / 132, cell = r % 132;
    int hp, wp;
    if (cell < 34)       { hp = 0;  wp = cell; }
    else if (cell < 68)  { hp = 33; wp = cell - 34; }
    else if (cell < 100) { hp = cell - 68 + 1;  wp = 0; }
    else                 { hp = cell - 100 + 1; wp = 33; }
    *(uint4*)&g_xh[((c * 34 + hp) * 34 + wp) * 64 + g8 * 8] = make_uint4(0, 0, 0, 0);
}

__global__ void transpose_kernel(const float* __restrict__ x) {
    __shared__ float t[32][65];
    int c = blockIdx.x & 63, h = blockIdx.x >> 6, tid = threadIdx.x;
    int w = tid & 31, b0 = tid >> 5;
#pragma unroll
    for (int p = 0; p < 8; p++)
        t[w][b0 * 8 + p] = x[(((b0 * 8 + p) * 64 + c) * 32 + h) * 32 + w];
    __syncthreads();
    int b = tid & 63, wq = tid >> 6;
#pragma unroll
    for (int p = 0; p < 8; p++) {
        int ww = wq * 8 + p;
        g_xh[((c * 34 + h + 1) * 34 + ww + 1) * 64 + b] = __float2half_rn(t[ww][b]);
    }
}

// ---------------------------------------------------------------------------
// lc_kernel: 128 CTAs = 64 l-tiles x 2 o-halves. CTA = 16 l x 32 o x 64 b.
// 512 threads = 16 warps; warp <-> pixel (M64 x N32 per pixel).
// ---------------------------------------------------------------------------
__global__ __launch_bounds__(512, 1)
void lc_kernel(const float* __restrict__ weight, const float* __restrict__ bias,
               float* __restrict__ out) {
    extern __shared__ uint32_t sm[];
    int* koff = (int*)(sm + KOFF_W);

    const int tid = threadIdx.x, lane = tid & 31, wrp = tid >> 5;
    const int l_tile = blockIdx.x >> 1, o0 = (blockIdx.x & 1) << 5;
    const int l0 = l_tile << 4;
    const int h = l0 >> 5, w0 = l0 & 31;            // l0 is 16-aligned: single h
    const int cq = lane & 3, rr = lane >> 2;

    for (int k = tid; k < 576; k += 512) {
        int c = k / 9, r = k - 9 * c, i = r / 3, j = r - 3 * i;
        koff[k] = (c * 1156 + i * 34 + j) * 64;     // half-element units
    }
    __syncthreads();

    // ---- u fill: warp = pixel; lanes = (qg = (lane>>3)&3, b8 = lane&7) ----
    const int u_qg = (tid >> 3) & 3, u_b8 = tid & 7;
    const __half* ubase = g_xh + (h * 34 + w0 + wrp) * 64 + u_b8 * 8;

    // ---- w fill: thread = (q0 = tid>>7, o = (tid>>2)&31, lq = tid&3) ----
    const int w_q0 = tid >> 7, w_o = (tid >> 2) & 31, w_lq = tid & 3;
    const float* wsrc = weight + (size_t)(o0 + w_o) * 576 * 1024 + l0 + w_lq * 4;

    uint4  ur[4];      // u staging: 2 q-groups x (k row, k+1 row), 8 halves each
    float4 wv[4];      // w staging: 2 q-groups x (k row, k+1 row), 4 l each

    auto ldg_u = [&](int ch) {
        int k0 = ch * 16 + 2 * u_qg;
        ur[0] = *(const uint4*)(ubase + koff[k0]);
        ur[1] = *(const uint4*)(ubase + koff[k0 + 1]);
        ur[2] = *(const uint4*)(ubase + koff[k0 + 8]);
        ur[3] = *(const uint4*)(ubase + koff[k0 + 9]);
    };
    auto ldg_w = [&](int ch) {
        int kb = ch * 16 + 2 * w_q0;
        wv[0] = *(const float4*)(wsrc + (size_t)kb * 1024);
        wv[1] = *(const float4*)(wsrc + (size_t)(kb + 1) * 1024);
        wv[2] = *(const float4*)(wsrc + (size_t)(kb + 8) * 1024);
        wv[3] = *(const float4*)(wsrc + (size_t)(kb + 9) * 1024);
    };
    auto sts_all = [&](int buf) {
        // u -> [l][q][b] half2, b padded 9-per-8 (word(b) = 9*(b>>3) + (b&7))
        uint32_t* du = sm + buf * SLOTW + wrp * UL + u_b8 * 9;
#pragma unroll
        for (int s = 0; s < 2; s++) {
            uint32_t* d = du + (u_qg + 4 * s) * UQ;
            uint4 r0 = ur[2 * s], r1 = ur[2 * s + 1];
            d[0] = prmt(r0.x, r1.x, 0x5410); d[1] = prmt(r0.x, r1.x, 0x7632);
            d[2] = prmt(r0.y, r1.y, 0x5410); d[3] = prmt(r0.y, r1.y, 0x7632);
            d[4] = prmt(r0.z, r1.z, 0x5410); d[5] = prmt(r0.z, r1.z, 0x7632);
            d[6] = prmt(r0.w, r1.w, 0x5410); d[7] = prmt(r0.w, r1.w, 0x7632);
        }
        // w -> [q][l][o] half2 (lo = k, hi = k+1)
        uint32_t* dw = sm + buf * SLOTW + UBUFW + (w_lq * 4) * WLS + w_o;
#pragma unroll
        for (int s = 0; s < 2; s++) {
            uint32_t* d = dw + (w_q0 + 4 * s) * WQS;
            float4 vk = wv[2 * s], vk1 = wv[2 * s + 1];
            d[0 * WLS] = f16x2(vk1.x, vk.x);
            d[1 * WLS] = f16x2(vk1.y, vk.y);
            d[2 * WLS] = f16x2(vk1.z, vk.z);
            d[3 * WLS] = f16x2(vk1.w, vk.w);
        }
    };

    float acc[16][4];
#pragma unroll
    for (int i = 0; i < 16; i++)
#pragma unroll
        for (int j = 0; j < 4; j++) acc[i][j] = 0.f;

    ldg_u(0); ldg_w(0);

    for (int ch = 0; ch < 36; ch++) {
        const int buf = ch & 1;
        sts_all(buf);
        __syncthreads();
        if (ch < 35) { ldg_u(ch + 1); ldg_w(ch + 1); }

        const uint32_t* A = sm + buf * SLOTW + wrp * UL + cq * UQ + rr;
        const uint32_t* B = sm + buf * SLOTW + UBUFW + cq * WQS + wrp * WLS + rr;
        uint32_t bfr[4][2];
#pragma unroll
        for (int nt = 0; nt < 4; nt++) {
            bfr[nt][0] = B[nt * 8];
            bfr[nt][1] = B[4 * WQS + nt * 8];
        }
#pragma unroll
        for (int mt = 0; mt < 4; mt++) {
            uint32_t ah[4];
            ah[0] = A[18 * mt];
            ah[1] = A[18 * mt + 9];
            ah[2] = A[4 * UQ + 18 * mt];
            ah[3] = A[4 * UQ + 18 * mt + 9];
#pragma unroll
            for (int nt = 0; nt < 4; nt++)
                MMAF16(acc[mt * 4 + nt], ah, bfr[nt]);
        }
        // single sync per chunk: buf rewritten 2 chunks later, after next sync
    }
    __syncthreads();

    // ---- epilogue: sep[pix][b][o] staging, then 64B coalesced rows ----
    float* sep = (float*)sm;
#pragma unroll
    for (int mt = 0; mt < 4; mt++)
#pragma unroll
        for (int nt = 0; nt < 4; nt++) {
            const float* d = acc[mt * 4 + nt];
            int b = mt * 16 + rr, o = nt * 8 + 2 * cq;
            float* p = sep + wrp * SEP_PS + b * SEP_BS + o;
            *(float2*)p                  = make_float2(d[0], d[1]);
            *(float2*)(p + 8 * SEP_BS)   = make_float2(d[2], d[3]);
        }
    __syncthreads();
#pragma unroll
    for (int it = 0; it < 4; it++) {
        int unit = tid + (it << 9);
        int o = unit & 31, b = unit >> 5;
        float v[16];
#pragma unroll
        for (int l = 0; l < 16; l++) v[l] = sep[l * SEP_PS + b * SEP_BS + o];
        const float* bp = bias + (size_t)(o0 + o) * 1024 + l0;
        float* dp = out + ((size_t)(b * 64 + o0 + o)) * 1024 + l0;
#pragma unroll
        for (int g = 0; g < 4; g++) {
            float4 bv = *(const float4*)(bp + 4 * g);
            *(float4*)(dp + 4 * g) = make_float4(v[4 * g] + bv.x, v[4 * g + 1] + bv.y,
                                                 v[4 * g + 2] + bv.z, v[4 * g + 3] + bv.w);
        }
    }
}

// ---------------------------------------------------------------------------
extern "C" void kernel_launch(void* const* d_in, const int* in_sizes, int n_in,
                              void* d_out, int out_size) {
    const float* x      = (const float*)d_in[0];
    const float* weight = (const float*)d_in[1];
    const float* bias   = (const float*)d_in[2];
    float* out = (float*)d_out;

    cudaFuncSetAttribute(lc_kernel, cudaFuncAttributeMaxDynamicSharedMemorySize, SMEM_BYTES);

    border_kernel<<<(64 * 132 * 8 + 255) / 256, 256>>>();
    transpose_kernel<<<64 * 32, 256>>>(x);
    lc_kernel<<<128, 512, SMEM_BYTES>>>(weight, bias, out);
}

// round 13
// speedup vs baseline: 2.2434x; 1.2853x over previous
#include <cuda_runtime.h>
#include <cuda_fp16.h>
#include <cstdint>

// ---- lc_kernel smem layout (32-bit words) ----
#define U_BUF_W   8192          // one u buffer: 16l*16k*128B = 32KB
#define WSM_OFF   24576         // after 3 u buffers
#define WQS 552                 // w q-stride (16*34 + 8)
#define WLS 34                  // w l-stride (32 o + 2 pad)
#define WBUFW 4416              // 8 * 552
#define KOFF_OFF  33408         // after 2 w buffers
#define SEP_BS 34
#define SEP_PS 2176             // 64 * 34
#define SMEM_BYTES (34816 * 4)  // epilogue staging is the max user

__device__ __align__(256) __half g_xh[64 * 34 * 34 * 64];  // [c][hp][wp][b] fp16

__device__ __forceinline__ uint32_t f16x2(float hi, float lo) {
    uint32_t d; asm("cvt.rn.f16x2.f32 %0,%1,%2;" : "=r"(d) : "f"(hi), "f"(lo)); return d;
}
__device__ __forceinline__ uint32_t s2u(const void* p) {
    uint32_t a;
    asm("{.reg .u64 t; cvta.to.shared.u64 t,%1; cvt.u32.u64 %0,t;}" : "=r"(a) : "l"(p));
    return a;
}
#define MMAF16(d, a, b) asm volatile( \
    "mma.sync.aligned.m16n8k16.row.col.f32.f16.f16.f32 " \
    "{%0,%1,%2,%3},{%4,%5,%6,%7},{%8,%9},{%0,%1,%2,%3};" \
    : "+f"((d)[0]), "+f"((d)[1]), "+f"((d)[2]), "+f"((d)[3]) \
    : "r"((a)[0]), "r"((a)[1]), "r"((a)[2]), "r"((a)[3]), "r"((b)[0]), "r"((b)[1]))

// ---------------------------------------------------------------------------
// prep_kernel: blocks [0,2048) transpose x -> g_xh; blocks [2048, 2312) zero
// the padded border.
// ---------------------------------------------------------------------------
__global__ void prep_kernel(const float* __restrict__ x) {
    int tid = threadIdx.x;
    if (blockIdx.x >= 2048) {
        int idx = (blockIdx.x - 2048) * 256 + tid;     // 64c * 132 cells * 8
        if (idx >= 64 * 132 * 8) return;
        int g8 = idx & 7, r = idx >> 3;
        int c = r / 132, cell = r % 132;
        int hp, wp;
        if (cell < 34)       { hp = 0;  wp = cell; }
        else if (cell < 68)  { hp = 33; wp = cell - 34; }
        else if (cell < 100) { hp = cell - 68 + 1;  wp = 0; }
        else                 { hp = cell - 100 + 1; wp = 33; }
        *(uint4*)&g_xh[((c * 34 + hp) * 34 + wp) * 64 + g8 * 8] = make_uint4(0, 0, 0, 0);
        return;
    }
    __shared__ float t[32][65];
    int c = blockIdx.x & 63, h = blockIdx.x >> 6;
    int w = tid & 31, b0 = tid >> 5;
#pragma unroll
    for (int p = 0; p < 8; p++)
        t[w][b0 * 8 + p] = x[(((b0 * 8 + p) * 64 + c) * 32 + h) * 32 + w];
    __syncthreads();
    int b = tid & 63, wq = tid >> 6;
#pragma unroll
    for (int p = 0; p < 8; p++) {
        int ww = wq * 8 + p;
        g_xh[((c * 34 + h + 1) * 34 + ww + 1) * 64 + b] = __float2half_rn(t[ww][b]);
    }
}

// ---------------------------------------------------------------------------
// lc_kernel: 128 CTAs = 64 l-tiles x 2 o-halves. CTA = 16 l x 32 o x 64 b.
// 512 threads = 16 warps; warp <-> pixel (M64(b) x N32(o) per pixel).
// u: cp.async (3-deep) -> swizzled [l][k][b] fp16 tile -> ldmatrix.x4.trans.
// w: LDG f32 -> cvt f16x2 -> STS (double-buffered).
// ---------------------------------------------------------------------------
__global__ __launch_bounds__(512, 1)
void lc_kernel(const float* __restrict__ weight, const float* __restrict__ bias,
               float* __restrict__ out) {
    extern __shared__ uint32_t sm[];
    uint32_t* wsm = sm + WSM_OFF;
    int* koff = (int*)(sm + KOFF_OFF);
    const uint32_t sbase = s2u(sm);

    const int tid = threadIdx.x, lane = tid & 31, wrp = tid >> 5;
    const int l_tile = blockIdx.x >> 1, o0 = (blockIdx.x & 1) << 5;
    const int l0 = l_tile << 4;
    const int h = l0 >> 5, w0 = l0 & 31;            // 16-aligned tile: single h
    const int cq = lane & 3, rr = lane >> 2;

    for (int k = tid; k < 576; k += 512) {
        int c = k / 9, r = k - 9 * c, i = r / 3, j = r - 3 * i;
        koff[k] = (c * 1156 + i * 34 + j) * 64;     // half-element units
    }

    // ---- u cp.async mapping: seg = tid&7, k = (tid>>3)&15, l = (tid>>7)+4i
    const int us8 = tid & 7, uk = (tid >> 3) & 15, ul = tid >> 7;
    const __half* usrc0 = g_xh + (h * 34 + w0 + ul) * 64 + us8 * 8;
    const uint32_t udst0 = sbase +
        (uint32_t)(ul * 2048 + uk * 128 + ((us8 ^ (uk & 7)) << 4));

    // ---- w fill: q0 = tid>>7, o = (tid>>2)&31, lq = tid&3 ----
    const int w_q0 = tid >> 7, w_o = (tid >> 2) & 31, w_lq = tid & 3;
    const float* wsrc = weight + (size_t)(o0 + w_o) * 576 * 1024 + l0 + w_lq * 4;

    // ---- ldmatrix lane mapping ----
    const int kr = (lane & 7) | ((lane & 16) >> 1);  // k-row 0..15
    const int bh = (lane >> 3) & 1;                  // b half (0: b0-7, 1: b8-15)
    const int k7 = kr & 7;
    const uint32_t lm_row = sbase + (uint32_t)(wrp * 2048 + kr * 128);

    float4 wv[4];
    auto issue_u = [&](int ch, int buf) {
        const __half* s = usrc0 + koff[ch * 16 + uk];
        uint32_t d = udst0 + (uint32_t)buf * 32768u;
#pragma unroll
        for (int i = 0; i < 4; i++)
            asm volatile("cp.async.cg.shared.global [%0],[%1],16;"
                         :: "r"(d + (uint32_t)i * 8192u), "l"(s + i * 256));
    };
    auto ldg_w = [&](int ch) {
        int kb = ch * 16 + 2 * w_q0;
        wv[0] = *(const float4*)(wsrc + (size_t)kb * 1024);
        wv[1] = *(const float4*)(wsrc + (size_t)(kb + 1) * 1024);
        wv[2] = *(const float4*)(wsrc + (size_t)(kb + 8) * 1024);
        wv[3] = *(const float4*)(wsrc + (size_t)(kb + 9) * 1024);
    };
    auto sts_w = [&](int buf) {
        uint32_t* dw = wsm + buf * WBUFW + (w_lq * 4) * WLS + w_o;
#pragma unroll
        for (int s = 0; s < 2; s++) {
            uint32_t* d = dw + (w_q0 + 4 * s) * WQS;
            float4 vk = wv[2 * s], vk1 = wv[2 * s + 1];
            d[0 * WLS] = f16x2(vk1.x, vk.x);
            d[1 * WLS] = f16x2(vk1.y, vk.y);
            d[2 * WLS] = f16x2(vk1.z, vk.z);
            d[3 * WLS] = f16x2(vk1.w, vk.w);
        }
    };

    float acc[16][4];
#pragma unroll
    for (int i = 0; i < 16; i++)
#pragma unroll
        for (int j = 0; j < 4; j++) acc[i][j] = 0.f;

    __syncthreads();                      // koff ready
    ldg_w(0);
    issue_u(0, 0); asm volatile("cp.async.commit_group;" ::: "memory");
    issue_u(1, 1); asm volatile("cp.async.commit_group;" ::: "memory");

    int ubm = 0;   // u buffer of chunk ch (mod 3)
    int ub2 = 2;   // u buffer of chunk ch+2 (mod 3)
    for (int ch = 0; ch < 36; ch++) {
        const int p = ch & 1;
        sts_w(p);
        if (ch + 2 < 36) issue_u(ch + 2, ub2);
        asm volatile("cp.async.commit_group;" ::: "memory");
        if (ch < 35) ldg_w(ch + 1);
        asm volatile("cp.async.wait_group 2;" ::: "memory");
        __syncthreads();

        // B fragments (w)
        const uint32_t* B = wsm + p * WBUFW + cq * WQS + wrp * WLS + rr;
        uint32_t bfr[4][2];
#pragma unroll
        for (int nt = 0; nt < 4; nt++) {
            bfr[nt][0] = B[nt * 8];
            bfr[nt][1] = B[4 * WQS + nt * 8];
        }
        // A fragments (u) via ldmatrix.trans + MMAs
        const uint32_t abase = lm_row + (uint32_t)ubm * 32768u;
#pragma unroll
        for (int mt = 0; mt < 4; mt++) {
            uint32_t a[4];
            uint32_t ad = abase + (uint32_t)((((2 * mt + bh) ^ k7) << 4));
            asm volatile("ldmatrix.sync.aligned.m8n8.x4.trans.shared.b16 "
                         "{%0,%1,%2,%3},[%4];"
                         : "=r"(a[0]), "=r"(a[1]), "=r"(a[2]), "=r"(a[3]) : "r"(ad));
#pragma unroll
            for (int nt = 0; nt < 4; nt++)
                MMAF16(acc[mt * 4 + nt], a, bfr[nt]);
        }
        ubm = (ubm == 2) ? 0 : ubm + 1;
        ub2 = (ub2 == 2) ? 0 : ub2 + 1;
        // single sync per chunk: w buf p rewritten at ch+2 (after sync ch+1);
        // u bufs are mod-3 so the cp.async issued above never targets a live buf.
    }
    __syncthreads();

    // ---- epilogue: sep[pix][b][o] staging, then 64B coalesced rows ----
    float* sep = (float*)sm;
#pragma unroll
    for (int mt = 0; mt < 4; mt++)
#pragma unroll
        for (int nt = 0; nt < 4; nt++) {
            const float* d = acc[mt * 4 + nt];
            int b = mt * 16 + rr, o = nt * 8 + 2 * cq;
            float* pp = sep + wrp * SEP_PS + b * SEP_BS + o;
            *(float2*)pp                = make_float2(d[0], d[1]);
            *(float2*)(pp + 8 * SEP_BS) = make_float2(d[2], d[3]);
        }
    __syncthreads();
#pragma unroll
    for (int it = 0; it < 4; it++) {
        int unit = tid + (it << 9);
        int o = unit & 31, b = unit >> 5;
        float v[16];
#pragma unroll
        for (int l = 0; l < 16; l++) v[l] = sep[l * SEP_PS + b * SEP_BS + o];
        const float* bp = bias + (size_t)(o0 + o) * 1024 + l0;
        float* dp = out + ((size_t)(b * 64 + o0 + o)) * 1024 + l0;
#pragma unroll
        for (int g = 0; g < 4; g++) {
            float4 bv = *(const float4*)(bp + 4 * g);
            *(float4*)(dp + 4 * g) = make_float4(v[4 * g] + bv.x, v[4 * g + 1] + bv.y,
                                                 v[4 * g + 2] + bv.z, v[4 * g + 3] + bv.w);
        }
    }
}

// ---------------------------------------------------------------------------
extern "C" void kernel_launch(void* const* d_in, const int* in_sizes, int n_in,
                              void* d_out, int out_size) {
    const float* x      = (const float*)d_in[0];
    const float* weight = (const float*)d_in[1];
    const float* bias   = (const float*)d_in[2];
    float* out = (float*)d_out;

    cudaFuncSetAttribute(lc_kernel, cudaFuncAttributeMaxDynamicSharedMemorySize, SMEM_BYTES);

    prep_kernel<<<2048 + 264, 256>>>(x);
    lc_kernel<<<128, 512, SMEM_BYTES>>>(weight, bias, out);
}